// round 6
// baseline (speedup 1.0000x reference)
#include <cuda_runtime.h>
#include <math.h>

// Problem constants
#define B    512
#define T    365
#define INP  10
#define H    256
#define OUT  20

// Decomposition: 4 batch groups x 32 column groups = 128 persistent CTAs
#define GB        4
#define GC        32
#define NCTA      (GB * GC)
#define NTHREADS  256
#define MB        128   // batch rows per CTA
#define HC        8     // h-columns per CTA (gate rows = 3*HC = 24)
#define WS        260   // padded smem weight row stride (floats)
#define KC        64    // k-chunk staged per round
#define NCH       (H / KC)   // 4 chunks
#define SS        68    // staged h row stride (floats)

// Persistent state (double buffered) + barrier counters. No allocs.
__device__ float g_h0[2][B * H];
__device__ float g_h1[2][B * H];
__device__ unsigned g_cnt[GB];
__device__ unsigned g_gen[GB];
__device__ unsigned g_cnt_all;
__device__ unsigned g_gen_all;

// Monotonic-generation barrier. Safe across launches: each thread reads gen
// BEFORE this CTA's arrival (gen for THIS barrier cannot advance until we
// arrive), then polls for any change. atomicInc wrap avoids the reset race.
__device__ __forceinline__ void barrier_sync(unsigned* cnt, unsigned* gen, unsigned wrap) {
    unsigned g;
    asm volatile("ld.acquire.gpu.global.u32 %0, [%1];" : "=r"(g) : "l"(gen) : "memory");
    __syncthreads();              // whole CTA done (incl. everyone's g-read)
    if (threadIdx.x == 0) {
        __threadfence();          // our writes visible before arrival
        if (atomicInc(cnt, wrap) == wrap) {
            __threadfence();      // cumulative: all arrivals' data before gen flip
            atomicAdd(gen, 1u);
        }
    }
    unsigned cur;
    do {
        asm volatile("ld.acquire.gpu.global.u32 %0, [%1];" : "=r"(cur) : "l"(gen) : "memory");
    } while (cur == g);
}

// Packed dual-FMA (Blackwell f32x2); ptxas never auto-fuses, explicit PTX.
__device__ __forceinline__ void ffma2(unsigned long long& d,
                                      unsigned long long a,
                                      unsigned long long b) {
    asm("fma.rn.f32x2 %0, %1, %2, %0;" : "+l"(d) : "l"(a), "l"(b));
}
__device__ __forceinline__ float accsum(unsigned long long a) {
    return __uint_as_float((unsigned)a) + __uint_as_float((unsigned)(a >> 32));
}

// Shared staging pass: stage hbase[MB][H] once, accumulate SIX gate rows
// (two weight sets A=W_hh0, B=W_ih1) for 4 batch rows. hold[] = h value at
// this thread's own column (read from staged smem, coalesced).
__device__ __forceinline__ void pass_dual(
    const float* __restrict__ hbase,
    float* __restrict__ sb0, float* __restrict__ sb1,
    const float* __restrict__ sWa, const float* __restrict__ sWb,
    int tid, int jc, int rg, int cch, int cloc,
    unsigned long long* __restrict__ accA,  // [g*4+r]
    unsigned long long* __restrict__ accB,  // [g*4+r]
    float* __restrict__ hold)               // [4]
{
    const int row_s = tid >> 4;      // 0..15
    const int col4  = tid & 15;      // 0..15
    float4 regs[8];
#pragma unroll
    for (int i = 0; i < 8; ++i)
        regs[i] = __ldcg(reinterpret_cast<const float4*>(
                      hbase + (size_t)(i * 16 + row_s) * H) + col4);
#pragma unroll
    for (int i = 0; i < 8; ++i)
        *reinterpret_cast<float4*>(sb0 + (i * 16 + row_s) * SS + col4 * 4) = regs[i];
    __syncthreads();

#pragma unroll
    for (int cc = 0; cc < NCH; ++cc) {
        float* cur = (cc & 1) ? sb1 : sb0;
        float* nxt = (cc & 1) ? sb0 : sb1;
        if (cc + 1 < NCH) {
#pragma unroll
            for (int i = 0; i < 8; ++i)
                regs[i] = __ldcg(reinterpret_cast<const float4*>(
                              hbase + (size_t)(i * 16 + row_s) * H + (cc + 1) * KC) + col4);
        }
        const ulonglong2* wa0 = (const ulonglong2*)(sWa + (0 * 8 + jc) * WS + cc * KC);
        const ulonglong2* wa1 = (const ulonglong2*)(sWa + (1 * 8 + jc) * WS + cc * KC);
        const ulonglong2* wa2 = (const ulonglong2*)(sWa + (2 * 8 + jc) * WS + cc * KC);
        const ulonglong2* wb0 = (const ulonglong2*)(sWb + (0 * 8 + jc) * WS + cc * KC);
        const ulonglong2* wb1 = (const ulonglong2*)(sWb + (1 * 8 + jc) * WS + cc * KC);
        const ulonglong2* wb2 = (const ulonglong2*)(sWb + (2 * 8 + jc) * WS + cc * KC);
        const ulonglong2* hp[4];
#pragma unroll
        for (int r = 0; r < 4; ++r)
            hp[r] = (const ulonglong2*)(cur + (rg + 32 * r) * SS);
#pragma unroll 4
        for (int k4 = 0; k4 < KC / 4; ++k4) {
            ulonglong2 a0 = wa0[k4], a1 = wa1[k4], a2 = wa2[k4];
            ulonglong2 b0 = wb0[k4], b1 = wb1[k4], b2 = wb2[k4];
#pragma unroll
            for (int r = 0; r < 4; ++r) {
                ulonglong2 hv = hp[r][k4];
                ffma2(accA[0 + r], hv.x, a0.x); ffma2(accA[0 + r], hv.y, a0.y);
                ffma2(accA[4 + r], hv.x, a1.x); ffma2(accA[4 + r], hv.y, a1.y);
                ffma2(accA[8 + r], hv.x, a2.x); ffma2(accA[8 + r], hv.y, a2.y);
                ffma2(accB[0 + r], hv.x, b0.x); ffma2(accB[0 + r], hv.y, b0.y);
                ffma2(accB[4 + r], hv.x, b1.x); ffma2(accB[4 + r], hv.y, b1.y);
                ffma2(accB[8 + r], hv.x, b2.x); ffma2(accB[8 + r], hv.y, b2.y);
            }
        }
        if (cc == cch) {
#pragma unroll
            for (int r = 0; r < 4; ++r)
                hold[r] = cur[(rg + 32 * r) * SS + cloc];
        }
        if (cc + 1 < NCH) {
#pragma unroll
            for (int i = 0; i < 8; ++i)
                *reinterpret_cast<float4*>(nxt + (i * 16 + row_s) * SS + col4 * 4) = regs[i];
            __syncthreads();
        }
    }
}

// Single-weight-set staging pass (W_hh1 . h1prev), 3 gate rows x 4 batch rows.
__device__ __forceinline__ void pass_single(
    const float* __restrict__ hbase,
    float* __restrict__ sb0, float* __restrict__ sb1,
    const float* __restrict__ sWa,
    int tid, int jc, int rg, int cch, int cloc,
    unsigned long long* __restrict__ accA, float* __restrict__ hold)
{
    const int row_s = tid >> 4;
    const int col4  = tid & 15;
    float4 regs[8];
#pragma unroll
    for (int i = 0; i < 8; ++i)
        regs[i] = __ldcg(reinterpret_cast<const float4*>(
                      hbase + (size_t)(i * 16 + row_s) * H) + col4);
#pragma unroll
    for (int i = 0; i < 8; ++i)
        *reinterpret_cast<float4*>(sb0 + (i * 16 + row_s) * SS + col4 * 4) = regs[i];
    __syncthreads();

#pragma unroll
    for (int cc = 0; cc < NCH; ++cc) {
        float* cur = (cc & 1) ? sb1 : sb0;
        float* nxt = (cc & 1) ? sb0 : sb1;
        if (cc + 1 < NCH) {
#pragma unroll
            for (int i = 0; i < 8; ++i)
                regs[i] = __ldcg(reinterpret_cast<const float4*>(
                              hbase + (size_t)(i * 16 + row_s) * H + (cc + 1) * KC) + col4);
        }
        const ulonglong2* wa0 = (const ulonglong2*)(sWa + (0 * 8 + jc) * WS + cc * KC);
        const ulonglong2* wa1 = (const ulonglong2*)(sWa + (1 * 8 + jc) * WS + cc * KC);
        const ulonglong2* wa2 = (const ulonglong2*)(sWa + (2 * 8 + jc) * WS + cc * KC);
        const ulonglong2* hp[4];
#pragma unroll
        for (int r = 0; r < 4; ++r)
            hp[r] = (const ulonglong2*)(cur + (rg + 32 * r) * SS);
#pragma unroll 4
        for (int k4 = 0; k4 < KC / 4; ++k4) {
            ulonglong2 a0 = wa0[k4], a1 = wa1[k4], a2 = wa2[k4];
#pragma unroll
            for (int r = 0; r < 4; ++r) {
                ulonglong2 hv = hp[r][k4];
                ffma2(accA[0 + r], hv.x, a0.x); ffma2(accA[0 + r], hv.y, a0.y);
                ffma2(accA[4 + r], hv.x, a1.x); ffma2(accA[4 + r], hv.y, a1.y);
                ffma2(accA[8 + r], hv.x, a2.x); ffma2(accA[8 + r], hv.y, a2.y);
            }
        }
        if (cc == cch) {
#pragma unroll
            for (int r = 0; r < 4; ++r)
                hold[r] = cur[(rg + 32 * r) * SS + cloc];
        }
        if (cc + 1 < NCH) {
#pragma unroll
            for (int i = 0; i < 8; ++i)
                *reinterpret_cast<float4*>(nxt + (i * 16 + row_s) * SS + col4 * 4) = regs[i];
            __syncthreads();
        }
    }
}

__device__ __forceinline__ float sigmoidf_(float v) {
    return 1.0f / (1.0f + expf(-v));
}

__global__ void __launch_bounds__(NTHREADS, 1)
gru_persistent_kernel(const float* __restrict__ x,
                      const float* __restrict__ W_ih0, const float* __restrict__ W_hh0,
                      const float* __restrict__ b_ih0, const float* __restrict__ b_hh0,
                      const float* __restrict__ W_ih1, const float* __restrict__ W_hh1,
                      const float* __restrict__ b_ih1, const float* __restrict__ b_hh1,
                      const float* __restrict__ W_out, const float* __restrict__ b_out,
                      float* __restrict__ out) {
    extern __shared__ float sm[];
    float* sWh0 = sm;                       // 24*WS
    float* sWi1 = sWh0 + 24 * WS;
    float* sWh1 = sWi1 + 24 * WS;
    float* sWi0 = sWh1 + 24 * WS;           // 24*12
    float* sBi0 = sWi0 + 24 * 12;           // 24 each
    float* sBh0 = sBi0 + 24;
    float* sBi1 = sBh0 + 24;
    float* sBh1 = sBi1 + 24;
    float* sx   = sBh1 + 24;                // MB*12 staged x tile
    float* sb0  = sx + MB * 12;             // staging buffer A (MB*SS)
    float* sb1  = sb0 + MB * SS;            // staging buffer B

    const int tid = threadIdx.x;
    const int gb  = blockIdx.x >> 5;        // batch group 0..3
    const int gc  = blockIdx.x & 31;        // column group 0..31
    const int c0  = gc * HC;
    const int jc  = tid & 7;                // h-column within CTA
    const int rg  = tid >> 3;               // 0..31; rows rg+32r
    const int c   = c0 + jc;                // global h column
    const int gb0 = gb * MB;                // CTA's first batch row
    const int cch = c0 >> 6;                // staging chunk holding column c
    const int cloc = (c0 & 63) + jc;        // column offset within that chunk

    // ---- Prologue: weights -> smem (resident all steps) ----
    for (int idx = tid; idx < 24 * 256; idx += NTHREADS) {
        int row = idx >> 8, k = idx & 255;
        int g = row >> 3, j = row & 7;
        int grow = g * H + c0 + j;
        sWh0[row * WS + k] = W_hh0[grow * H + k];
        sWi1[row * WS + k] = W_ih1[grow * H + k];
        sWh1[row * WS + k] = W_hh1[grow * H + k];
    }
    for (int idx = tid; idx < 24 * INP; idx += NTHREADS) {
        int row = idx / INP, i = idx - row * INP;
        int g = row >> 3, j = row & 7;
        int grow = g * H + c0 + j;
        sWi0[row * 12 + i] = W_ih0[grow * INP + i];
    }
    if (tid < 24) {
        int g = tid >> 3, j = tid & 7;
        int grow = g * H + c0 + j;
        sBi0[tid] = b_ih0[grow];
        sBh0[tid] = b_hh0[grow];
        sBi1[tid] = b_ih1[grow];
        sBh1[tid] = b_hh1[grow];
    }

    // Zero the initial-state buffers read at i=0 / i=1.
    for (int idx = blockIdx.x * NTHREADS + tid; idx < B * H; idx += NCTA * NTHREADS) {
        __stcg(&g_h0[1][idx], 0.0f);
        __stcg(&g_h1[1][idx], 0.0f);
    }
    barrier_sync(&g_cnt_all, &g_gen_all, NCTA - 1);

    // ---- Pipelined main loop: iter i computes h0[i] (layer0) and h1[i-1]
    //      (layer1). Both consume only pre-barrier state -> ONE barrier/iter.
    for (int i = 0; i <= T; ++i) {
        const float* h0r = g_h0[(i + 1) & 1];   // h0[i-1]
        float*       h0w = g_h0[i & 1];         // h0[i]
        const float* h1r = g_h1[i & 1];         // h1[i-2]
        float*       h1w = g_h1[(i + 1) & 1];   // h1[i-1]

        // Stage x[t] tile (coalesced). Visibility via pass_dual's first sync.
        if (i < T) {
            for (int idx = tid; idx < MB * INP; idx += NTHREADS) {
                int row = idx / INP, k = idx - row * INP;
                sx[row * 12 + k] = __ldg(&x[((size_t)(gb0 + row) * T + i) * INP + k]);
            }
        }

        // Pass 1 (shared): accA = W_hh0 . h0[i-1], accB = W_ih1 . h0[i-1]
        unsigned long long accA[12], accB[12];
#pragma unroll
        for (int q = 0; q < 12; ++q) { accA[q] = 0ull; accB[q] = 0ull; }
        float h0old[4];
        pass_dual(h0r + (size_t)gb0 * H, sb0, sb1, sWh0, sWi1,
                  tid, jc, rg, cch, cloc, accA, accB, h0old);

        // Layer-0 update -> h0[i]
        if (i < T) {
#pragma unroll
            for (int r = 0; r < 4; ++r) {
                int lr = rg + 32 * r;
                float air = sBi0[0 * 8 + jc], aiz = sBi0[1 * 8 + jc], ain = sBi0[2 * 8 + jc];
#pragma unroll
                for (int k = 0; k < INP; ++k) {
                    float xv = sx[lr * 12 + k];
                    air += xv * sWi0[(0 * 8 + jc) * 12 + k];
                    aiz += xv * sWi0[(1 * 8 + jc) * 12 + k];
                    ain += xv * sWi0[(2 * 8 + jc) * 12 + k];
                }
                float gr = accsum(accA[0 + r]) + sBh0[0 * 8 + jc];
                float gz = accsum(accA[4 + r]) + sBh0[1 * 8 + jc];
                float gn = accsum(accA[8 + r]) + sBh0[2 * 8 + jc];
                float rr = sigmoidf_(air + gr);
                float zz = sigmoidf_(aiz + gz);
                float nn = tanhf(ain + rr * gn);
                __stcg(&h0w[(size_t)(gb0 + lr) * H + c],
                       (1.0f - zz) * nn + zz * h0old[r]);
            }
        }

        // Pass 2: accC = W_hh1 . h1[i-2];  layer-1 update -> h1[i-1]
        if (i >= 1) {
            unsigned long long accC[12];
#pragma unroll
            for (int q = 0; q < 12; ++q) accC[q] = 0ull;
            float h1old[4];
            pass_single(h1r + (size_t)gb0 * H, sb0, sb1, sWh1,
                        tid, jc, rg, cch, cloc, accC, h1old);
#pragma unroll
            for (int r = 0; r < 4; ++r) {
                float ir = accsum(accB[0 + r]) + sBi1[0 * 8 + jc];
                float iz = accsum(accB[4 + r]) + sBi1[1 * 8 + jc];
                float in = accsum(accB[8 + r]) + sBi1[2 * 8 + jc];
                float hr = accsum(accC[0 + r]) + sBh1[0 * 8 + jc];
                float hz = accsum(accC[4 + r]) + sBh1[1 * 8 + jc];
                float hn = accsum(accC[8 + r]) + sBh1[2 * 8 + jc];
                float rr = sigmoidf_(ir + hr);
                float zz = sigmoidf_(iz + hz);
                float nn = tanhf(in + rr * hn);
                __stcg(&h1w[(size_t)(gb0 + rg + 32 * r) * H + c],
                       (1.0f - zz) * nn + zz * h1old[r]);
            }
        }

        barrier_sync(&g_cnt[gb], &g_gen[gb], GC - 1);
    }

    // Epilogue reads rows across batch groups -> global barrier.
    barrier_sync(&g_cnt_all, &g_gen_all, NCTA - 1);

    // ---- Epilogue: logits + softmax, one warp per batch row ----
    const float* hfin = g_h1[(T + 1) & 1];   // h1[T-1]
    int gw = blockIdx.x * (NTHREADS / 32) + (tid >> 5);
    int lane = tid & 31;
    if (gw < B) {
        const float* hrow = hfin + (size_t)gw * H;
        float hk[8];
#pragma unroll
        for (int j2 = 0; j2 < 8; ++j2) hk[j2] = __ldcg(&hrow[lane + 32 * j2]);

        float logits[OUT];
#pragma unroll
        for (int o = 0; o < OUT; ++o) {
            float p = 0.0f;
#pragma unroll
            for (int j2 = 0; j2 < 8; ++j2)
                p += hk[j2] * __ldg(&W_out[o * H + lane + 32 * j2]);
#pragma unroll
            for (int s = 16; s > 0; s >>= 1)
                p += __shfl_xor_sync(0xffffffffu, p, s);
            logits[o] = p + __ldg(&b_out[o]);
        }
        float mx = logits[0];
#pragma unroll
        for (int o = 1; o < OUT; ++o) mx = fmaxf(mx, logits[o]);
        float sum = 0.0f;
#pragma unroll
        for (int o = 0; o < OUT; ++o) { logits[o] = expf(logits[o] - mx); sum += logits[o]; }
        float inv = 1.0f / sum;
        if (lane == 0) {
#pragma unroll
            for (int o = 0; o < OUT; ++o)
                out[(size_t)gw * OUT + o] = logits[o] * inv;
        }
    }
}

extern "C" void kernel_launch(void* const* d_in, const int* in_sizes, int n_in,
                              void* d_out, int out_size) {
    const float* x      = (const float*)d_in[0];
    // d_in[1] = times (unused), d_in[2] = interpolation_method (unused)
    const float* W_ih0  = (const float*)d_in[3];
    const float* W_hh0  = (const float*)d_in[4];
    const float* b_ih0  = (const float*)d_in[5];
    const float* b_hh0  = (const float*)d_in[6];
    const float* W_ih1  = (const float*)d_in[7];
    const float* W_hh1  = (const float*)d_in[8];
    const float* b_ih1  = (const float*)d_in[9];
    const float* b_hh1  = (const float*)d_in[10];
    const float* W_out  = (const float*)d_in[11];
    const float* b_out  = (const float*)d_in[12];
    float* out = (float*)d_out;

    const size_t smem_bytes =
        (size_t)(3 * 24 * WS + 24 * 12 + 4 * 24 + MB * 12 + 2 * MB * SS) * sizeof(float);
    cudaFuncSetAttribute(gru_persistent_kernel,
                         cudaFuncAttributeMaxDynamicSharedMemorySize, (int)smem_bytes);

    gru_persistent_kernel<<<NCTA, NTHREADS, smem_bytes>>>(
        x, W_ih0, W_hh0, b_ih0, b_hh0,
        W_ih1, W_hh1, b_ih1, b_hh1,
        W_out, b_out, out);
}

// round 7
// speedup vs baseline: 1.3689x; 1.3689x over previous
#include <cuda_runtime.h>
#include <math.h>

// Problem constants
#define B    512
#define T    365
#define INP  10
#define H    256
#define OUT  20

// 4 batch groups x 32 column groups = 128 persistent CTAs.
// 512 threads = 2 k-split teams of 256; each team: 8 jc x 32 rg, 4 rows/thread.
#define GB        4
#define GC        32
#define NCTA      (GB * GC)
#define NTHREADS  512
#define MB        128   // batch rows per CTA
#define HC        8     // h-columns per CTA (gate rows = 3*HC = 24)
#define WS        260   // padded smem weight row stride (floats)
#define KC        64    // k-chunk per staging slot
#define SS        68    // staged h row stride (floats), conflict-free
#define RS        13    // reduction row stride (gcd(13,32)=1 -> conflict-free)

// Persistent state (double buffered) + barrier counters. No allocs.
__device__ float g_h0[2][B * H];
__device__ float g_h1[2][B * H];
__device__ unsigned g_cnt[GB];
__device__ unsigned g_gen[GB];
__device__ unsigned g_cnt_all;
__device__ unsigned g_gen_all;

__device__ __forceinline__ void barrier_sync(unsigned* cnt, unsigned* gen, unsigned target) {
    __threadfence();          // all threads: our writes visible
    __syncthreads();
    if (threadIdx.x == 0) {
        unsigned g = *(volatile unsigned*)gen;
        if (atomicAdd(cnt, 1u) == target - 1u) {
            *cnt = 0u;
            __threadfence();
            atomicAdd(gen, 1u);
        } else {
            while (*(volatile unsigned*)gen == g) { }
        }
    }
    __syncthreads();
}

// Packed dual-FMA (Blackwell f32x2); ptxas never auto-fuses, explicit PTX.
__device__ __forceinline__ void ffma2(unsigned long long& d,
                                      unsigned long long a,
                                      unsigned long long b) {
    asm("fma.rn.f32x2 %0, %1, %2, %0;" : "+l"(d) : "l"(a), "l"(b));
}
__device__ __forceinline__ float accsum(unsigned long long a) {
    return __uint_as_float((unsigned)a) + __uint_as_float((unsigned)(a >> 32));
}

// 64-k-wide chunk: 3 gates x 4 rows, packed k-pairs. sWk already includes the
// k offset; weight rows stride WS. h rows rg+32r in sb (stride SS).
__device__ __forceinline__ void compute_chunk(
    const float* __restrict__ sb, const float* __restrict__ sWk,
    int jc, int rg, unsigned long long* __restrict__ acc /*[12]*/) {
    const ulonglong2* __restrict__ w0 = (const ulonglong2*)(sWk + (0 * 8 + jc) * WS);
    const ulonglong2* __restrict__ w1 = (const ulonglong2*)(sWk + (1 * 8 + jc) * WS);
    const ulonglong2* __restrict__ w2 = (const ulonglong2*)(sWk + (2 * 8 + jc) * WS);
    const ulonglong2* __restrict__ h0 = (const ulonglong2*)(sb + (rg + 0)  * SS);
    const ulonglong2* __restrict__ h1 = (const ulonglong2*)(sb + (rg + 32) * SS);
    const ulonglong2* __restrict__ h2 = (const ulonglong2*)(sb + (rg + 64) * SS);
    const ulonglong2* __restrict__ h3 = (const ulonglong2*)(sb + (rg + 96) * SS);
#pragma unroll 4
    for (int k4 = 0; k4 < KC / 4; ++k4) {
        ulonglong2 a0 = w0[k4], a1 = w1[k4], a2 = w2[k4];
        ulonglong2 v0 = h0[k4], v1 = h1[k4], v2 = h2[k4], v3 = h3[k4];
        ffma2(acc[0],  v0.x, a0.x); ffma2(acc[0],  v0.y, a0.y);
        ffma2(acc[1],  v1.x, a0.x); ffma2(acc[1],  v1.y, a0.y);
        ffma2(acc[2],  v2.x, a0.x); ffma2(acc[2],  v2.y, a0.y);
        ffma2(acc[3],  v3.x, a0.x); ffma2(acc[3],  v3.y, a0.y);
        ffma2(acc[4],  v0.x, a1.x); ffma2(acc[4],  v0.y, a1.y);
        ffma2(acc[5],  v1.x, a1.x); ffma2(acc[5],  v1.y, a1.y);
        ffma2(acc[6],  v2.x, a1.x); ffma2(acc[6],  v2.y, a1.y);
        ffma2(acc[7],  v3.x, a1.x); ffma2(acc[7],  v3.y, a1.y);
        ffma2(acc[8],  v0.x, a2.x); ffma2(acc[8],  v0.y, a2.y);
        ffma2(acc[9],  v1.x, a2.x); ffma2(acc[9],  v1.y, a2.y);
        ffma2(acc[10], v2.x, a2.x); ffma2(acc[10], v2.y, a2.y);
        ffma2(acc[11], v3.x, a2.x); ffma2(acc[11], v3.y, a2.y);
    }
}

// One k-split pass over hbase[MB][H]: team 0 covers k [0,128) via sb0,
// team 1 covers k [128,256) via sb1. Both teams stage their chunks
// concurrently; 3 __syncthreads total. hold[] (team 0 only): h at this
// thread's own column, grabbed from whichever buffer/slot holds chunk cch.
__device__ __forceinline__ void pass_ks(
    const float* __restrict__ hbase,
    float* __restrict__ sb0, float* __restrict__ sb1,
    const float* __restrict__ sW,
    int t2, int team, int jc, int rg, int cch, int cloc, int want_hold,
    unsigned long long* __restrict__ acc, float* __restrict__ hold) {
    float* sb = team ? sb1 : sb0;
    const int row_s = t2 >> 4;     // 0..15
    const int col4  = t2 & 15;     // 0..15
    const int cb    = team * 2;    // team's first chunk index

    float4 regs[8];
#pragma unroll
    for (int i = 0; i < 8; ++i)
        regs[i] = __ldcg(reinterpret_cast<const float4*>(
                      hbase + (size_t)(i * 16 + row_s) * H + cb * KC) + col4);
#pragma unroll
    for (int i = 0; i < 8; ++i)
        *reinterpret_cast<float4*>(sb + (i * 16 + row_s) * SS + col4 * 4) = regs[i];
    __syncthreads();               // slot 0 (both buffers) visible

    // prefetch slot 1 while computing slot 0
#pragma unroll
    for (int i = 0; i < 8; ++i)
        regs[i] = __ldcg(reinterpret_cast<const float4*>(
                      hbase + (size_t)(i * 16 + row_s) * H + (cb + 1) * KC) + col4);

    compute_chunk(sb, sW + cb * KC, jc, rg, acc);
    if (want_hold && !team && (cch & 1) == 0) {
        const float* hb = (cch < 2) ? sb0 : sb1;
#pragma unroll
        for (int r = 0; r < 4; ++r) hold[r] = hb[(rg + 32 * r) * SS + cloc];
    }
    __syncthreads();               // slot 0 consumed (incl. hold reads)

#pragma unroll
    for (int i = 0; i < 8; ++i)
        *reinterpret_cast<float4*>(sb + (i * 16 + row_s) * SS + col4 * 4) = regs[i];
    __syncthreads();               // slot 1 visible

    compute_chunk(sb, sW + (cb + 1) * KC, jc, rg, acc);
    if (want_hold && !team && (cch & 1) == 1) {
        const float* hb = (cch < 2) ? sb0 : sb1;
#pragma unroll
        for (int r = 0; r < 4; ++r) hold[r] = hb[(rg + 32 * r) * SS + cloc];
    }
}

// Cross-team reduction: team 1 publishes its 12 partials; team 0 accumulates.
__device__ __forceinline__ void reduce_sums(
    const unsigned long long* __restrict__ acc, float* __restrict__ red,
    int t2, int team, float* __restrict__ s) {
#pragma unroll
    for (int q = 0; q < 12; ++q) s[q] = accsum(acc[q]);
    if (team) {
#pragma unroll
        for (int q = 0; q < 12; ++q) red[t2 * RS + q] = s[q];
    }
    __syncthreads();
    if (!team) {
#pragma unroll
        for (int q = 0; q < 12; ++q) s[q] += red[t2 * RS + q];
    }
}

__device__ __forceinline__ float sigmoidf_(float v) {
    return 1.0f / (1.0f + expf(-v));
}

__global__ void __launch_bounds__(NTHREADS, 1)
gru_persistent_kernel(const float* __restrict__ x,
                      const float* __restrict__ W_ih0, const float* __restrict__ W_hh0,
                      const float* __restrict__ b_ih0, const float* __restrict__ b_hh0,
                      const float* __restrict__ W_ih1, const float* __restrict__ W_hh1,
                      const float* __restrict__ b_ih1, const float* __restrict__ b_hh1,
                      const float* __restrict__ W_out, const float* __restrict__ b_out,
                      float* __restrict__ out) {
    extern __shared__ float sm[];
    float* sWh0 = sm;                       // 24*WS
    float* sWi1 = sWh0 + 24 * WS;
    float* sWh1 = sWi1 + 24 * WS;
    float* sWi0 = sWh1 + 24 * WS;           // 24*12
    float* sBi0 = sWi0 + 24 * 12;           // 24 each
    float* sBh0 = sBi0 + 24;
    float* sBi1 = sBh0 + 24;
    float* sBh1 = sBi1 + 24;
    float* sx   = sBh1 + 24;                // MB*12
    float* sb0  = sx + MB * 12;             // team-0 staging (MB*SS)
    float* sb1  = sb0 + MB * SS;            // team-1 staging
    float* red  = sb1 + MB * SS;            // 256*RS reduction buffer

    const int tid  = threadIdx.x;
    const int team = tid >> 8;              // 0 or 1 (k-split)
    const int t2   = tid & 255;
    const int gb   = blockIdx.x >> 5;       // batch group 0..3
    const int gc   = blockIdx.x & 31;       // column group 0..31
    const int c0   = gc * HC;
    const int jc   = t2 & 7;                // h-column within CTA
    const int rg   = t2 >> 3;               // 0..31; rows rg+32r
    const int c    = c0 + jc;               // global h column
    const int gb0  = gb * MB;               // CTA's first batch row
    const int cch  = c0 >> 6;               // chunk index holding column c
    const int cloc = (c0 & 63) + jc;        // column offset within that chunk

    // ---- Prologue: weights -> smem (resident all 365 steps) ----
    for (int idx = tid; idx < 24 * 256; idx += NTHREADS) {
        int row = idx >> 8, k = idx & 255;
        int g = row >> 3, j = row & 7;
        int grow = g * H + c0 + j;
        sWh0[row * WS + k] = W_hh0[grow * H + k];
        sWi1[row * WS + k] = W_ih1[grow * H + k];
        sWh1[row * WS + k] = W_hh1[grow * H + k];
    }
    for (int idx = tid; idx < 24 * INP; idx += NTHREADS) {
        int row = idx / INP, i = idx - row * INP;
        int g = row >> 3, j = row & 7;
        int grow = g * H + c0 + j;
        sWi0[row * 12 + i] = W_ih0[grow * INP + i];
    }
    if (tid < 24) {
        int g = tid >> 3, j = tid & 7;
        int grow = g * H + c0 + j;
        sBi0[tid] = b_ih0[grow];
        sBh0[tid] = b_hh0[grow];
        sBi1[tid] = b_ih1[grow];
        sBh1[tid] = b_hh1[grow];
    }

    // Zero initial hidden state (read at t=0). Every launch (determinism).
    for (int idx = blockIdx.x * NTHREADS + tid; idx < B * H; idx += NCTA * NTHREADS) {
        __stcg(&g_h0[0][idx], 0.0f);
        __stcg(&g_h1[0][idx], 0.0f);
    }
    barrier_sync(&g_cnt_all, &g_gen_all, NCTA);

    // ---- Main sequential loop ----
    for (int t = 0; t < T; ++t) {
        const float* h0r = g_h0[t & 1];
        float*       h0w = g_h0[(t & 1) ^ 1];
        const float* h1r = g_h1[t & 1];
        float*       h1w = g_h1[(t & 1) ^ 1];

        // Stage x[t] tile (coalesced); visible at pass1's first sync.
        for (int idx = tid; idx < MB * INP; idx += NTHREADS) {
            int row = idx / INP, k = idx - row * INP;
            sx[row * 12 + k] = __ldg(&x[((size_t)(gb0 + row) * T + t) * INP + k]);
        }

        // ===== Pass 1: W_hh0 . h0[t-1] =====
        unsigned long long accA[12];
#pragma unroll
        for (int q = 0; q < 12; ++q) accA[q] = 0ull;
        float h0old[4];
        pass_ks(h0r + (size_t)gb0 * H, sb0, sb1, sWh0,
                t2, team, jc, rg, cch, cloc, 1, accA, h0old);
        float sA[12];
        reduce_sums(accA, red, t2, team, sA);

        // Layer-0 gates (team 0 only; team 1 proceeds into pass 2 staging)
        if (!team) {
#pragma unroll
            for (int r = 0; r < 4; ++r) {
                int lr = rg + 32 * r;
                float air = sBi0[jc], aiz = sBi0[8 + jc], ain = sBi0[16 + jc];
#pragma unroll
                for (int k = 0; k < INP; ++k) {
                    float xv = sx[lr * 12 + k];
                    air += xv * sWi0[(0 * 8 + jc) * 12 + k];
                    aiz += xv * sWi0[(1 * 8 + jc) * 12 + k];
                    ain += xv * sWi0[(2 * 8 + jc) * 12 + k];
                }
                float rr = sigmoidf_(air + sA[0 + r] + sBh0[jc]);
                float zz = sigmoidf_(aiz + sA[4 + r] + sBh0[8 + jc]);
                float nn = tanhf(ain + rr * (sA[8 + r] + sBh0[16 + jc]));
                __stcg(&h0w[(size_t)(gb0 + lr) * H + c],
                       (1.0f - zz) * nn + zz * h0old[r]);
            }
        }

        // ===== Pass 2: W_hh1 . h1[t-1] (pre-barrier overlap) =====
        unsigned long long accC[12];
#pragma unroll
        for (int q = 0; q < 12; ++q) accC[q] = 0ull;
        float h1old[4];
        pass_ks(h1r + (size_t)gb0 * H, sb0, sb1, sWh1,
                t2, team, jc, rg, cch, cloc, 1, accC, h1old);
        float sC[12];
        reduce_sums(accC, red, t2, team, sC);

        barrier_sync(&g_cnt[gb], &g_gen[gb], GC);   // h0[t] visible group-wide

        // ===== Pass 3: W_ih1 . h0[t] =====
        unsigned long long accB[12];
#pragma unroll
        for (int q = 0; q < 12; ++q) accB[q] = 0ull;
        pass_ks(h0w + (size_t)gb0 * H, sb0, sb1, sWi1,
                t2, team, jc, rg, cch, cloc, 0, accB, h0old);
        float sB_[12];
        reduce_sums(accB, red, t2, team, sB_);

        if (!team) {
#pragma unroll
            for (int r = 0; r < 4; ++r) {
                float rr = sigmoidf_(sB_[0 + r] + sBi1[jc]      + sC[0 + r] + sBh1[jc]);
                float zz = sigmoidf_(sB_[4 + r] + sBi1[8 + jc]  + sC[4 + r] + sBh1[8 + jc]);
                float nn = tanhf(sB_[8 + r] + sBi1[16 + jc]
                                 + rr * (sC[8 + r] + sBh1[16 + jc]));
                __stcg(&h1w[(size_t)(gb0 + rg + 32 * r) * H + c],
                       (1.0f - zz) * nn + zz * h1old[r]);
            }
        }

        barrier_sync(&g_cnt[gb], &g_gen[gb], GC);   // h1[t] visible group-wide
    }

    // Epilogue reads rows across batch groups -> global barrier.
    barrier_sync(&g_cnt_all, &g_gen_all, NCTA);

    // ---- Epilogue: logits + softmax, one warp per batch row ----
    const float* hfin = g_h1[T & 1];
    int gw = blockIdx.x * (NTHREADS / 32) + (tid >> 5);
    int lane = tid & 31;
    if (gw < B) {
        const float* hrow = hfin + (size_t)gw * H;
        float hk[8];
#pragma unroll
        for (int j2 = 0; j2 < 8; ++j2) hk[j2] = __ldcg(&hrow[lane + 32 * j2]);

        float logits[OUT];
#pragma unroll
        for (int o = 0; o < OUT; ++o) {
            float p = 0.0f;
#pragma unroll
            for (int j2 = 0; j2 < 8; ++j2)
                p += hk[j2] * __ldg(&W_out[o * H + lane + 32 * j2]);
#pragma unroll
            for (int s = 16; s > 0; s >>= 1)
                p += __shfl_xor_sync(0xffffffffu, p, s);
            logits[o] = p + __ldg(&b_out[o]);
        }
        float mx = logits[0];
#pragma unroll
        for (int o = 1; o < OUT; ++o) mx = fmaxf(mx, logits[o]);
        float sum = 0.0f;
#pragma unroll
        for (int o = 0; o < OUT; ++o) { logits[o] = expf(logits[o] - mx); sum += logits[o]; }
        float inv = 1.0f / sum;
        if (lane == 0) {
#pragma unroll
            for (int o = 0; o < OUT; ++o)
                out[(size_t)gw * OUT + o] = logits[o] * inv;
        }
    }
}

extern "C" void kernel_launch(void* const* d_in, const int* in_sizes, int n_in,
                              void* d_out, int out_size) {
    const float* x      = (const float*)d_in[0];
    // d_in[1] = times (unused), d_in[2] = interpolation_method (unused)
    const float* W_ih0  = (const float*)d_in[3];
    const float* W_hh0  = (const float*)d_in[4];
    const float* b_ih0  = (const float*)d_in[5];
    const float* b_hh0  = (const float*)d_in[6];
    const float* W_ih1  = (const float*)d_in[7];
    const float* W_hh1  = (const float*)d_in[8];
    const float* b_ih1  = (const float*)d_in[9];
    const float* b_hh1  = (const float*)d_in[10];
    const float* W_out  = (const float*)d_in[11];
    const float* b_out  = (const float*)d_in[12];
    float* out = (float*)d_out;

    const size_t smem_bytes =
        (size_t)(3 * 24 * WS + 24 * 12 + 4 * 24 + MB * 12
                 + 2 * MB * SS + 256 * RS) * sizeof(float);   // ~166 KB
    cudaFuncSetAttribute(gru_persistent_kernel,
                         cudaFuncAttributeMaxDynamicSharedMemorySize, (int)smem_bytes);

    gru_persistent_kernel<<<NCTA, NTHREADS, smem_bytes>>>(
        x, W_ih0, W_hh0, b_ih0, b_hh0,
        W_ih1, W_hh1, b_ih1, b_hh1,
        W_out, b_out, out);
}

// round 8
// speedup vs baseline: 3.2423x; 2.3685x over previous
#include <cuda_runtime.h>
#include <cuda_bf16.h>
#include <math.h>

// Problem constants
#define B    512
#define T    365
#define INP  10
#define H    256
#define OUT  20

// 4 batch groups x 32 column groups = 128 persistent CTAs, 256 thr = 8 warps.
// Warp w = M-tile w (16 batch rows); CTA covers 128 rows x 8 h-cols (24 gate rows = 3 N-tiles).
#define GB        4
#define GC        32
#define NCTA      (GB * GC)
#define NTHREADS  256

// A-fragment arrays in global: [buf2][gb4][mtile8][kstep16][split2][lane32] x uint4(16B)
#define HA_ELEMS  (2 * 4 * 8 * 16 * 2 * 32)   // 65536 uint4 = 1 MB per layer

__device__ uint4 g_hA0[HA_ELEMS];
__device__ uint4 g_hA1[HA_ELEMS];
__device__ float g_hfin[B * H];
__device__ unsigned g_cnt[GB];
__device__ unsigned g_gen[GB];
__device__ unsigned g_cnt_all;
__device__ unsigned g_gen_all;

__device__ __forceinline__ int ha_idx(int buf, int gb, int mt, int ks, int sp, int l) {
    return (((((buf * 4 + gb) * 8 + mt) * 16 + ks) * 2 + sp) * 32 + l);
}

__device__ __forceinline__ void barrier_sync(unsigned* cnt, unsigned* gen, unsigned target) {
    __threadfence();
    __syncthreads();
    if (threadIdx.x == 0) {
        unsigned g = *(volatile unsigned*)gen;
        if (atomicAdd(cnt, 1u) == target - 1u) {
            *cnt = 0u;
            __threadfence();
            atomicAdd(gen, 1u);
        } else {
            while (*(volatile unsigned*)gen == g) { }
        }
    }
    __syncthreads();
}

// mma.sync m16n8k16 row.col f32.bf16.bf16.f32, accumulate in place.
__device__ __forceinline__ void mma_bf16(float* d, unsigned a0, unsigned a1,
                                         unsigned a2, unsigned a3,
                                         unsigned b0, unsigned b1) {
    asm volatile(
        "mma.sync.aligned.m16n8k16.row.col.f32.bf16.bf16.f32 "
        "{%0,%1,%2,%3}, {%4,%5,%6,%7}, {%8,%9}, {%0,%1,%2,%3};"
        : "+f"(d[0]), "+f"(d[1]), "+f"(d[2]), "+f"(d[3])
        : "r"(a0), "r"(a1), "r"(a2), "r"(a3), "r"(b0), "r"(b1));
}

// Split two fp32 into packed bf16x2 (hi) + packed bf16x2 (lo residual).
__device__ __forceinline__ void split2(float a, float b, unsigned& hi, unsigned& lo) {
    __nv_bfloat16 ah = __float2bfloat16_rn(a), bh = __float2bfloat16_rn(b);
    __nv_bfloat16 al = __float2bfloat16_rn(a - __bfloat162float(ah));
    __nv_bfloat16 bl = __float2bfloat16_rn(b - __bfloat162float(bh));
    __nv_bfloat162 h2; h2.x = ah; h2.y = bh;
    __nv_bfloat162 l2; l2.x = al; l2.y = bl;
    hi = *reinterpret_cast<unsigned*>(&h2);
    lo = *reinterpret_cast<unsigned*>(&l2);
}

__device__ __forceinline__ float sigmoidf_(float v) {
    return 1.0f / (1.0f + expf(-v));
}

// Weight-fragment smem: 3 sets (hh0, hh1, ih1) x 3 ntiles x 16 ksteps x 32 lanes,
// uint4 = {b0_hi, b1_hi, b0_lo, b1_lo}. 4608 x 16B = 72 KB.
#define NWB (3 * 3 * 16 * 32)

__global__ void __launch_bounds__(NTHREADS, 1)
gru_tc_kernel(const float* __restrict__ x,
              const float* __restrict__ W_ih0, const float* __restrict__ W_hh0,
              const float* __restrict__ b_ih0, const float* __restrict__ b_hh0,
              const float* __restrict__ W_ih1, const float* __restrict__ W_hh1,
              const float* __restrict__ b_ih1, const float* __restrict__ b_hh1,
              const float* __restrict__ W_out, const float* __restrict__ b_out,
              float* __restrict__ out) {
    extern __shared__ char smraw[];
    uint4* sWB  = reinterpret_cast<uint4*>(smraw);     // NWB
    float* sx   = reinterpret_cast<float*>(sWB + NWB); // 128*12
    float* sWi0 = sx + 128 * 12;                       // 24*12
    float* sBi0 = sWi0 + 24 * 12;                      // 24 each
    float* sBh0 = sBi0 + 24;
    float* sBi1 = sBh0 + 24;
    float* sBh1 = sBi1 + 24;

    const int tid = threadIdx.x;
    const int w   = tid >> 5;              // warp = M-tile 0..7
    const int l   = tid & 31;              // lane
    const int g   = l >> 2;                // frag row group 0..7
    const int c   = l & 3;                 // frag col pair 0..3
    const int gb  = blockIdx.x >> 5;       // batch group
    const int gc  = blockIdx.x & 31;       // column group
    const int c0  = gc * 8;
    const int gb0 = gb * 128;
    const int ksW = gc >> 1;               // kstep our h-cols land in
    const int wboff = 8 * (gc & 1);        // byte offset within the 16B frag slot

    // ---- Prologue: pack weights into B-fragment layout (hi/lo split) ----
    {
        const float* Wsets[3] = { W_hh0, W_hh1, W_ih1 };
        for (int e = tid; e < NWB; e += NTHREADS) {
            int lane = e & 31;
            int ks   = (e >> 5) & 15;
            int rest = e >> 9;
            int n    = rest % 3;     // gate / N-tile
            int s    = rest / 3;     // weight set
            int t4 = lane & 3, nn = lane >> 2;
            const float* Wp = Wsets[s] + (size_t)(n * H + c0 + nn) * H + ks * 16;
            float w00 = Wp[2 * t4],     w01 = Wp[2 * t4 + 1];
            float w10 = Wp[8 + 2 * t4], w11 = Wp[9 + 2 * t4];
            uint4 v;
            split2(w00, w01, v.x, v.z);
            split2(w10, w11, v.y, v.w);
            sWB[e] = v;
        }
    }
    // x-projection weights + biases (24 gate rows of this CTA)
    for (int idx = tid; idx < 24 * INP; idx += NTHREADS) {
        int row = idx / INP, i = idx - row * INP;
        int gg = row >> 3, j = row & 7;
        sWi0[row * 12 + i] = W_ih0[(gg * H + c0 + j) * INP + i];
    }
    if (tid < 24) {
        int gg = tid >> 3, j = tid & 7;
        int grow = gg * H + c0 + j;
        sBi0[tid] = b_ih0[grow];
        sBh0[tid] = b_hh0[grow];
        sBi1[tid] = b_ih1[grow];
        sBh1[tid] = b_hh1[grow];
    }

    // Zero A-frag buffers (h=0 at t=0); every launch for determinism.
    {
        uint4 z4 = make_uint4(0u, 0u, 0u, 0u);
        for (int i = blockIdx.x * NTHREADS + tid; i < HA_ELEMS; i += NCTA * NTHREADS) {
            g_hA0[i] = z4;
            g_hA1[i] = z4;
        }
    }
    barrier_sync(&g_cnt_all, &g_gen_all, NCTA);

    // Persistent per-thread hidden state: 4 positions =
    // (row g, col 2c), (g, 2c+1), (g+8, 2c), (g+8, 2c+1) of (mtile w, CTA cols).
    float h0reg[4] = {0.f, 0.f, 0.f, 0.f};
    float h1reg[4] = {0.f, 0.f, 0.f, 0.f};

    for (int t = 0; t < T; ++t) {
        const int bufR = t & 1, bufW = bufR ^ 1;

        // Stage x[t] tile for this CTA's 128 rows (coalesced).
        for (int i = tid; i < 128 * INP; i += NTHREADS) {
            int row = i / INP, k = i - row * INP;
            sx[row * 12 + k] = __ldg(&x[((size_t)(gb0 + row) * T + t) * INP + k]);
        }
        __syncthreads();

        // ===== Phase 1: acc0 = W_hh0.h0[t-1], acc1 = W_hh1.h1[t-1] =====
        float acc0[3][4] = {}, acc1[3][4] = {};
        {
            const uint4* pA0 = g_hA0 + ha_idx(bufR, gb, w, 0, 0, 0);
            const uint4* pA1 = g_hA1 + ha_idx(bufR, gb, w, 0, 0, 0);
#pragma unroll
            for (int ks = 0; ks < 16; ++ks) {
                uint4 a0h = __ldcg(pA0 + ks * 64 + l);
                uint4 a0l = __ldcg(pA0 + ks * 64 + 32 + l);
                uint4 a1h = __ldcg(pA1 + ks * 64 + l);
                uint4 a1l = __ldcg(pA1 + ks * 64 + 32 + l);
#pragma unroll
                for (int n = 0; n < 3; ++n) {
                    uint4 wb0 = sWB[((0 * 3 + n) * 16 + ks) * 32 + l];
                    mma_bf16(acc0[n], a0h.x, a0h.y, a0h.z, a0h.w, wb0.x, wb0.y);
                    mma_bf16(acc0[n], a0h.x, a0h.y, a0h.z, a0h.w, wb0.z, wb0.w);
                    mma_bf16(acc0[n], a0l.x, a0l.y, a0l.z, a0l.w, wb0.x, wb0.y);
                    uint4 wb1 = sWB[((1 * 3 + n) * 16 + ks) * 32 + l];
                    mma_bf16(acc1[n], a1h.x, a1h.y, a1h.z, a1h.w, wb1.x, wb1.y);
                    mma_bf16(acc1[n], a1h.x, a1h.y, a1h.z, a1h.w, wb1.z, wb1.w);
                    mma_bf16(acc1[n], a1l.x, a1l.y, a1l.z, a1l.w, wb1.x, wb1.y);
                }
            }
        }

        // Layer-0 gate update -> h0[t] (lane-local; D frag p = 2*rowbit + slot)
#pragma unroll
        for (int p = 0; p < 4; ++p) {
            int rb = p >> 1, sl = p & 1;
            int lrow = w * 16 + g + 8 * rb;
            int jc = 2 * c + sl;
            float xr = 0.f, xz = 0.f, xn = 0.f;
#pragma unroll
            for (int k = 0; k < INP; ++k) {
                float xv = sx[lrow * 12 + k];
                xr += xv * sWi0[(0 * 8 + jc) * 12 + k];
                xz += xv * sWi0[(1 * 8 + jc) * 12 + k];
                xn += xv * sWi0[(2 * 8 + jc) * 12 + k];
            }
            float rr = sigmoidf_(xr + sBi0[jc]      + acc0[0][p] + sBh0[jc]);
            float zz = sigmoidf_(xz + sBi0[8 + jc]  + acc0[1][p] + sBh0[8 + jc]);
            float nn = tanhf(xn + sBi0[16 + jc] + rr * (acc0[2][p] + sBh0[16 + jc]));
            h0reg[p] = (1.0f - zz) * nn + zz * h0reg[p];
        }
        // Publish h0[t] as A-fragments (hi/lo bf16), coalesced-ish STG.64.
        {
            unsigned hi01, lo01, hi23, lo23;
            split2(h0reg[0], h0reg[1], hi01, lo01);
            split2(h0reg[2], h0reg[3], hi23, lo23);
            char* bh = (char*)(g_hA0 + ha_idx(bufW, gb, w, ksW, 0, l)) + wboff;
            char* bl = (char*)(g_hA0 + ha_idx(bufW, gb, w, ksW, 1, l)) + wboff;
            __stcg((unsigned long long*)bh,
                   ((unsigned long long)hi23 << 32) | hi01);
            __stcg((unsigned long long*)bl,
                   ((unsigned long long)lo23 << 32) | lo01);
        }

        barrier_sync(&g_cnt[gb], &g_gen[gb], GC);   // h0[t] frags visible in group

        // ===== Phase 2: acc2 = W_ih1 . h0[t] =====
        float acc2[3][4] = {};
        {
            const uint4* pA2 = g_hA0 + ha_idx(bufW, gb, w, 0, 0, 0);
#pragma unroll
            for (int ks = 0; ks < 16; ++ks) {
                uint4 ah = __ldcg(pA2 + ks * 64 + l);
                uint4 al = __ldcg(pA2 + ks * 64 + 32 + l);
#pragma unroll
                for (int n = 0; n < 3; ++n) {
                    uint4 wb = sWB[((2 * 3 + n) * 16 + ks) * 32 + l];
                    mma_bf16(acc2[n], ah.x, ah.y, ah.z, ah.w, wb.x, wb.y);
                    mma_bf16(acc2[n], ah.x, ah.y, ah.z, ah.w, wb.z, wb.w);
                    mma_bf16(acc2[n], al.x, al.y, al.z, al.w, wb.x, wb.y);
                }
            }
        }

        // Layer-1 gate update -> h1[t]
#pragma unroll
        for (int p = 0; p < 4; ++p) {
            int jc = 2 * c + (p & 1);
            float rr = sigmoidf_(acc2[0][p] + sBi1[jc]     + acc1[0][p] + sBh1[jc]);
            float zz = sigmoidf_(acc2[1][p] + sBi1[8 + jc] + acc1[1][p] + sBh1[8 + jc]);
            float nn = tanhf(acc2[2][p] + sBi1[16 + jc]
                             + rr * (acc1[2][p] + sBh1[16 + jc]));
            h1reg[p] = (1.0f - zz) * nn + zz * h1reg[p];
        }
        {
            unsigned hi01, lo01, hi23, lo23;
            split2(h1reg[0], h1reg[1], hi01, lo01);
            split2(h1reg[2], h1reg[3], hi23, lo23);
            char* bh = (char*)(g_hA1 + ha_idx(bufW, gb, w, ksW, 0, l)) + wboff;
            char* bl = (char*)(g_hA1 + ha_idx(bufW, gb, w, ksW, 1, l)) + wboff;
            __stcg((unsigned long long*)bh,
                   ((unsigned long long)hi23 << 32) | hi01);
            __stcg((unsigned long long*)bl,
                   ((unsigned long long)lo23 << 32) | lo01);
        }
        if (t == T - 1) {
#pragma unroll
            for (int p = 0; p < 4; ++p) {
                int row = gb0 + w * 16 + g + 8 * (p >> 1);
                int col = c0 + 2 * c + (p & 1);
                __stcg(&g_hfin[(size_t)row * H + col], h1reg[p]);
            }
        }

        barrier_sync(&g_cnt[gb], &g_gen[gb], GC);   // h1[t] frags visible in group
    }

    // Epilogue needs h1 across all groups.
    barrier_sync(&g_cnt_all, &g_gen_all, NCTA);

    // ---- logits + softmax, one warp per batch row ----
    int gw = blockIdx.x * (NTHREADS / 32) + w;
    if (gw < B) {
        const float* hrow = g_hfin + (size_t)gw * H;
        float hk[8];
#pragma unroll
        for (int j2 = 0; j2 < 8; ++j2) hk[j2] = __ldcg(&hrow[l + 32 * j2]);

        float logits[OUT];
#pragma unroll
        for (int o = 0; o < OUT; ++o) {
            float p = 0.0f;
#pragma unroll
            for (int j2 = 0; j2 < 8; ++j2)
                p += hk[j2] * __ldg(&W_out[o * H + l + 32 * j2]);
#pragma unroll
            for (int s = 16; s > 0; s >>= 1)
                p += __shfl_xor_sync(0xffffffffu, p, s);
            logits[o] = p + __ldg(&b_out[o]);
        }
        float mx = logits[0];
#pragma unroll
        for (int o = 1; o < OUT; ++o) mx = fmaxf(mx, logits[o]);
        float sum = 0.0f;
#pragma unroll
        for (int o = 0; o < OUT; ++o) { logits[o] = expf(logits[o] - mx); sum += logits[o]; }
        float inv = 1.0f / sum;
        if (l == 0) {
#pragma unroll
            for (int o = 0; o < OUT; ++o)
                out[(size_t)gw * OUT + o] = logits[o] * inv;
        }
    }
}

extern "C" void kernel_launch(void* const* d_in, const int* in_sizes, int n_in,
                              void* d_out, int out_size) {
    const float* x      = (const float*)d_in[0];
    // d_in[1] = times (unused), d_in[2] = interpolation_method (unused)
    const float* W_ih0  = (const float*)d_in[3];
    const float* W_hh0  = (const float*)d_in[4];
    const float* b_ih0  = (const float*)d_in[5];
    const float* b_hh0  = (const float*)d_in[6];
    const float* W_ih1  = (const float*)d_in[7];
    const float* W_hh1  = (const float*)d_in[8];
    const float* b_ih1  = (const float*)d_in[9];
    const float* b_hh1  = (const float*)d_in[10];
    const float* W_out  = (const float*)d_in[11];
    const float* b_out  = (const float*)d_in[12];
    float* out = (float*)d_out;

    const size_t smem_bytes = (size_t)NWB * 16
        + (size_t)(128 * 12 + 24 * 12 + 4 * 24) * sizeof(float);   // ~81.4 KB
    cudaFuncSetAttribute(gru_tc_kernel,
                         cudaFuncAttributeMaxDynamicSharedMemorySize, (int)smem_bytes);

    gru_tc_kernel<<<NCTA, NTHREADS, smem_bytes>>>(
        x, W_ih0, W_hh0, b_ih0, b_hh0,
        W_ih1, W_hh1, b_ih1, b_hh1,
        W_out, b_out, out);
}

// round 9
// speedup vs baseline: 3.8460x; 1.1862x over previous
#include <cuda_runtime.h>
#include <cuda_bf16.h>
#include <math.h>

// Problem constants
#define B    512
#define T    365
#define INP  10
#define H    256
#define OUT  20

// 4 batch groups x 32 column groups = 128 persistent CTAs, 256 thr = 8 warps.
// Warp w = M-tile (16 batch rows); CTA covers 128 rows x 8 h-cols (3 N-tiles).
#define GB        4
#define GC        32
#define NCTA      (GB * GC)
#define NTHREADS  256

// A-fragment arrays in global: [buf2][gb4][mtile8][kstep16][split2][lane32] x uint4
#define HA_ELEMS  (2 * 4 * 8 * 16 * 2 * 32)

__device__ uint4 g_hA0[HA_ELEMS];
__device__ uint4 g_hA1[HA_ELEMS];
__device__ float g_hfin[B * H];
__device__ unsigned g_cnt[GB];
__device__ unsigned g_gen[GB];
__device__ unsigned g_cnt_all;
__device__ unsigned g_gen_all;

__device__ __forceinline__ int ha_idx(int buf, int gb, int mt, int ks, int sp, int l) {
    return (((((buf * 4 + gb) * 8 + mt) * 16 + ks) * 2 + sp) * 32 + l);
}

__device__ __forceinline__ void barrier_sync(unsigned* cnt, unsigned* gen, unsigned target) {
    __threadfence();
    __syncthreads();
    if (threadIdx.x == 0) {
        unsigned g = *(volatile unsigned*)gen;
        if (atomicAdd(cnt, 1u) == target - 1u) {
            *cnt = 0u;
            __threadfence();
            atomicAdd(gen, 1u);
        } else {
            while (*(volatile unsigned*)gen == g) { }
        }
    }
    __syncthreads();
}

// mma.sync m16n8k16 row.col f32.bf16.bf16.f32, accumulate in place.
__device__ __forceinline__ void mma_bf16(float* d, unsigned a0, unsigned a1,
                                         unsigned a2, unsigned a3,
                                         unsigned b0, unsigned b1) {
    asm volatile(
        "mma.sync.aligned.m16n8k16.row.col.f32.bf16.bf16.f32 "
        "{%0,%1,%2,%3}, {%4,%5,%6,%7}, {%8,%9}, {%0,%1,%2,%3};"
        : "+f"(d[0]), "+f"(d[1]), "+f"(d[2]), "+f"(d[3])
        : "r"(a0), "r"(a1), "r"(a2), "r"(a3), "r"(b0), "r"(b1));
}

// Split two fp32 into packed bf16x2 (hi) + packed bf16x2 (lo residual).
__device__ __forceinline__ void split2(float a, float b, unsigned& hi, unsigned& lo) {
    __nv_bfloat16 ah = __float2bfloat16_rn(a), bh = __float2bfloat16_rn(b);
    __nv_bfloat16 al = __float2bfloat16_rn(a - __bfloat162float(ah));
    __nv_bfloat16 bl = __float2bfloat16_rn(b - __bfloat162float(bh));
    __nv_bfloat162 h2; h2.x = ah; h2.y = bh;
    __nv_bfloat162 l2; l2.x = al; l2.y = bl;
    hi = *reinterpret_cast<unsigned*>(&h2);
    lo = *reinterpret_cast<unsigned*>(&l2);
}

__device__ __forceinline__ float sigmoidf_(float v) {
    return 1.0f / (1.0f + expf(-v));
}

// Weight-fragment smem: sets s (0=hh0, 1=hh1, 2=ih1) x 3 ntiles x 16 ksteps x 32 lanes,
// uint4 = {b0_hi, b1_hi, b0_lo, b1_lo}. 4608 x 16B = 72 KB.
#define NWB (3 * 3 * 16 * 32)

__global__ void __launch_bounds__(NTHREADS, 1)
gru_tc_kernel(const float* __restrict__ x,
              const float* __restrict__ W_ih0, const float* __restrict__ W_hh0,
              const float* __restrict__ b_ih0, const float* __restrict__ b_hh0,
              const float* __restrict__ W_ih1, const float* __restrict__ W_hh1,
              const float* __restrict__ b_ih1, const float* __restrict__ b_hh1,
              const float* __restrict__ W_out, const float* __restrict__ b_out,
              float* __restrict__ out) {
    extern __shared__ char smraw[];
    uint4* sWB  = reinterpret_cast<uint4*>(smraw);     // NWB
    float* sx   = reinterpret_cast<float*>(sWB + NWB); // 128*12
    float* sWi0 = sx + 128 * 12;                       // 24*12
    float* sBi0 = sWi0 + 24 * 12;                      // 24 each
    float* sBh0 = sBi0 + 24;
    float* sBi1 = sBh0 + 24;
    float* sBh1 = sBi1 + 24;

    const int tid = threadIdx.x;
    const int w   = tid >> 5;              // warp = M-tile 0..7
    const int l   = tid & 31;              // lane
    const int g   = l >> 2;                // frag row group 0..7
    const int c   = l & 3;                 // frag col pair 0..3
    const int gb  = blockIdx.x >> 5;       // batch group
    const int gc  = blockIdx.x & 31;       // column group
    const int c0  = gc * 8;
    const int gb0 = gb * 128;
    const int ksW = gc >> 1;               // kstep our h-cols land in
    const int wboff = 8 * (gc & 1);        // byte offset within the 16B frag slot

    // ---- Prologue: pack weights into B-fragment layout (hi/lo split) ----
    {
        const float* Wsets[3] = { W_hh0, W_hh1, W_ih1 };
        for (int e = tid; e < NWB; e += NTHREADS) {
            int lane = e & 31;
            int ks   = (e >> 5) & 15;
            int rest = e >> 9;
            int n    = rest % 3;     // gate / N-tile
            int s    = rest / 3;     // weight set
            int t4 = lane & 3, nn = lane >> 2;
            const float* Wp = Wsets[s] + (size_t)(n * H + c0 + nn) * H + ks * 16;
            float w00 = Wp[2 * t4],     w01 = Wp[2 * t4 + 1];
            float w10 = Wp[8 + 2 * t4], w11 = Wp[9 + 2 * t4];
            uint4 v;
            split2(w00, w01, v.x, v.z);
            split2(w10, w11, v.y, v.w);
            sWB[e] = v;
        }
    }
    for (int idx = tid; idx < 24 * INP; idx += NTHREADS) {
        int row = idx / INP, i = idx - row * INP;
        int gg = row >> 3, j = row & 7;
        sWi0[row * 12 + i] = W_ih0[(gg * H + c0 + j) * INP + i];
    }
    if (tid < 24) {
        int gg = tid >> 3, j = tid & 7;
        int grow = gg * H + c0 + j;
        sBi0[tid] = b_ih0[grow];
        sBh0[tid] = b_hh0[grow];
        sBi1[tid] = b_ih1[grow];
        sBh1[tid] = b_hh1[grow];
    }

    // Zero A-frag buffers (h0[-1] = h1[-1] = h1[-2] = 0). Every launch.
    {
        uint4 z4 = make_uint4(0u, 0u, 0u, 0u);
        for (int i = blockIdx.x * NTHREADS + tid; i < HA_ELEMS; i += NCTA * NTHREADS) {
            g_hA0[i] = z4;
            g_hA1[i] = z4;
        }
    }
    barrier_sync(&g_cnt_all, &g_gen_all, NCTA);

    // Per-thread persistent hidden state (4 D-frag positions each).
    float h0reg[4] = {0.f, 0.f, 0.f, 0.f};
    float h1reg[4] = {0.f, 0.f, 0.f, 0.f};

    // ---- Pipelined loop: iter i computes h0[i] AND h1[i-1]; ONE barrier/iter.
    //      Reads (all post-barrier i-1): h0[i-1] frags, h1[i-2] frags.
    for (int i = 0; i <= T; ++i) {
        const int bufR = i & 1, bufW = bufR ^ 1;

        if (i < T) {
            for (int e = tid; e < 128 * INP; e += NTHREADS) {
                int row = e / INP, k = e - row * INP;
                sx[row * 12 + k] = __ldg(&x[((size_t)(gb0 + row) * T + i) * INP + k]);
            }
            __syncthreads();
        }

        // One fused mma stream: acc[s*3+n]; s: 0=hh0(a0), 1=hh1(a1), 2=ih1(a0)
        float acc[9][4] = {};
        {
            const uint4* pA0 = g_hA0 + ha_idx(bufR, gb, w, 0, 0, 0);
            const uint4* pA1 = g_hA1 + ha_idx(bufR, gb, w, 0, 0, 0);
#pragma unroll 4
            for (int ks = 0; ks < 16; ++ks) {
                uint4 a0h = __ldcg(pA0 + ks * 64 + l);
                uint4 a0l = __ldcg(pA0 + ks * 64 + 32 + l);
                uint4 a1h = __ldcg(pA1 + ks * 64 + l);
                uint4 a1l = __ldcg(pA1 + ks * 64 + 32 + l);
#pragma unroll
                for (int n = 0; n < 3; ++n) {
                    uint4 wb0 = sWB[((0 * 3 + n) * 16 + ks) * 32 + l];
                    mma_bf16(acc[0 + n], a0h.x, a0h.y, a0h.z, a0h.w, wb0.x, wb0.y);
                    mma_bf16(acc[0 + n], a0h.x, a0h.y, a0h.z, a0h.w, wb0.z, wb0.w);
                    mma_bf16(acc[0 + n], a0l.x, a0l.y, a0l.z, a0l.w, wb0.x, wb0.y);
                    uint4 wb1 = sWB[((1 * 3 + n) * 16 + ks) * 32 + l];
                    mma_bf16(acc[3 + n], a1h.x, a1h.y, a1h.z, a1h.w, wb1.x, wb1.y);
                    mma_bf16(acc[3 + n], a1h.x, a1h.y, a1h.z, a1h.w, wb1.z, wb1.w);
                    mma_bf16(acc[3 + n], a1l.x, a1l.y, a1l.z, a1l.w, wb1.x, wb1.y);
                    uint4 wb2 = sWB[((2 * 3 + n) * 16 + ks) * 32 + l];
                    mma_bf16(acc[6 + n], a0h.x, a0h.y, a0h.z, a0h.w, wb2.x, wb2.y);
                    mma_bf16(acc[6 + n], a0h.x, a0h.y, a0h.z, a0h.w, wb2.z, wb2.w);
                    mma_bf16(acc[6 + n], a0l.x, a0l.y, a0l.z, a0l.w, wb2.x, wb2.y);
                }
            }
        }

        // Layer-0 update -> h0[i]; publish frags.
        if (i < T) {
#pragma unroll
            for (int p = 0; p < 4; ++p) {
                int rb = p >> 1, sl = p & 1;
                int lrow = w * 16 + g + 8 * rb;
                int jc = 2 * c + sl;
                float xr = 0.f, xz = 0.f, xn = 0.f;
#pragma unroll
                for (int k = 0; k < INP; ++k) {
                    float xv = sx[lrow * 12 + k];
                    xr += xv * sWi0[(0 * 8 + jc) * 12 + k];
                    xz += xv * sWi0[(1 * 8 + jc) * 12 + k];
                    xn += xv * sWi0[(2 * 8 + jc) * 12 + k];
                }
                float rr = sigmoidf_(xr + sBi0[jc]     + acc[0][p] + sBh0[jc]);
                float zz = sigmoidf_(xz + sBi0[8 + jc] + acc[1][p] + sBh0[8 + jc]);
                float nn = tanhf(xn + sBi0[16 + jc] + rr * (acc[2][p] + sBh0[16 + jc]));
                h0reg[p] = (1.0f - zz) * nn + zz * h0reg[p];
            }
            unsigned hi01, lo01, hi23, lo23;
            split2(h0reg[0], h0reg[1], hi01, lo01);
            split2(h0reg[2], h0reg[3], hi23, lo23);
            char* bh = (char*)(g_hA0 + ha_idx(bufW, gb, w, ksW, 0, l)) + wboff;
            char* bl = (char*)(g_hA0 + ha_idx(bufW, gb, w, ksW, 1, l)) + wboff;
            __stcg((unsigned long long*)bh, ((unsigned long long)hi23 << 32) | hi01);
            __stcg((unsigned long long*)bl, ((unsigned long long)lo23 << 32) | lo01);
        }

        // Layer-1 update -> h1[i-1]; publish frags.
        if (i >= 1) {
#pragma unroll
            for (int p = 0; p < 4; ++p) {
                int jc = 2 * c + (p & 1);
                float rr = sigmoidf_(acc[6][p] + sBi1[jc]     + acc[3][p] + sBh1[jc]);
                float zz = sigmoidf_(acc[7][p] + sBi1[8 + jc] + acc[4][p] + sBh1[8 + jc]);
                float nn = tanhf(acc[8][p] + sBi1[16 + jc]
                                 + rr * (acc[5][p] + sBh1[16 + jc]));
                h1reg[p] = (1.0f - zz) * nn + zz * h1reg[p];
            }
            unsigned hi01, lo01, hi23, lo23;
            split2(h1reg[0], h1reg[1], hi01, lo01);
            split2(h1reg[2], h1reg[3], hi23, lo23);
            char* bh = (char*)(g_hA1 + ha_idx(bufW, gb, w, ksW, 0, l)) + wboff;
            char* bl = (char*)(g_hA1 + ha_idx(bufW, gb, w, ksW, 1, l)) + wboff;
            __stcg((unsigned long long*)bh, ((unsigned long long)hi23 << 32) | hi01);
            __stcg((unsigned long long*)bl, ((unsigned long long)lo23 << 32) | lo01);
            if (i == T) {
#pragma unroll
                for (int p = 0; p < 4; ++p) {
                    int row = gb0 + w * 16 + g + 8 * (p >> 1);
                    int col = c0 + 2 * c + (p & 1);
                    __stcg(&g_hfin[(size_t)row * H + col], h1reg[p]);
                }
            }
        }

        barrier_sync(&g_cnt[gb], &g_gen[gb], GC);
    }

    // Epilogue needs h1 across all groups.
    barrier_sync(&g_cnt_all, &g_gen_all, NCTA);

    // ---- logits + softmax, one warp per batch row ----
    int gw = blockIdx.x * (NTHREADS / 32) + w;
    if (gw < B) {
        const float* hrow = g_hfin + (size_t)gw * H;
        float hk[8];
#pragma unroll
        for (int j2 = 0; j2 < 8; ++j2) hk[j2] = __ldcg(&hrow[l + 32 * j2]);

        float logits[OUT];
#pragma unroll
        for (int o = 0; o < OUT; ++o) {
            float p = 0.0f;
#pragma unroll
            for (int j2 = 0; j2 < 8; ++j2)
                p += hk[j2] * __ldg(&W_out[o * H + l + 32 * j2]);
#pragma unroll
            for (int s = 16; s > 0; s >>= 1)
                p += __shfl_xor_sync(0xffffffffu, p, s);
            logits[o] = p + __ldg(&b_out[o]);
        }
        float mx = logits[0];
#pragma unroll
        for (int o = 1; o < OUT; ++o) mx = fmaxf(mx, logits[o]);
        float sum = 0.0f;
#pragma unroll
        for (int o = 0; o < OUT; ++o) { logits[o] = expf(logits[o] - mx); sum += logits[o]; }
        float inv = 1.0f / sum;
        if (l == 0) {
#pragma unroll
            for (int o = 0; o < OUT; ++o)
                out[(size_t)gw * OUT + o] = logits[o] * inv;
        }
    }
}

extern "C" void kernel_launch(void* const* d_in, const int* in_sizes, int n_in,
                              void* d_out, int out_size) {
    const float* x      = (const float*)d_in[0];
    // d_in[1] = times (unused), d_in[2] = interpolation_method (unused)
    const float* W_ih0  = (const float*)d_in[3];
    const float* W_hh0  = (const float*)d_in[4];
    const float* b_ih0  = (const float*)d_in[5];
    const float* b_hh0  = (const float*)d_in[6];
    const float* W_ih1  = (const float*)d_in[7];
    const float* W_hh1  = (const float*)d_in[8];
    const float* b_ih1  = (const float*)d_in[9];
    const float* b_hh1  = (const float*)d_in[10];
    const float* W_out  = (const float*)d_in[11];
    const float* b_out  = (const float*)d_in[12];
    float* out = (float*)d_out;

    const size_t smem_bytes = (size_t)NWB * 16
        + (size_t)(128 * 12 + 24 * 12 + 4 * 24) * sizeof(float);   // ~81.4 KB
    cudaFuncSetAttribute(gru_tc_kernel,
                         cudaFuncAttributeMaxDynamicSharedMemorySize, (int)smem_bytes);

    gru_tc_kernel<<<NCTA, NTHREADS, smem_bytes>>>(
        x, W_ih0, W_hh0, b_ih0, b_hh0,
        W_ih1, W_hh1, b_ih1, b_hh1,
        W_out, b_out, out);
}